// round 12
// baseline (speedup 1.0000x reference)
#include <cuda_runtime.h>
#include <cstdint>

// ---------------- problem constants ----------------
#define NT   2048
#define HD   2048
#define NE   8
#define FF   1408
#define FSS  2816
#define TMR  128
#define CAPTILES 40
#define CAP (CAPTILES * TMR)

#define KCH   32           // K elements per pipeline stage
#define ROWB  80u          // padded smem row bytes (64B data + 16B pad)
#define PL    10240u       // plane bytes = 128 rows * 80B
#define STG_UP (6u * PL)
#define STG_DN (4u * PL)
#define UP_SMEM (3 * 61440 + 4096)
#define DN_SMEM (3 * 40960 + 4096)

// scale constants (chosen from reference init distributions)
#define SH_X   32.0f        // x hi scale (|x|<~5.5 -> <176)
#define SL_X   16384.0f     // x lo scale = SH*512
#define SH_W   2048.0f      // weight hi scale (|w|<~0.15 -> <307)
#define SL_W   1048576.0f
#define SH_H1  8.0f         // h1 hi scale (|h1|<~50 -> <400)
#define SL_H1  4096.0f
#define ISC_UP 2.9802322387695312e-8f   // 2^-25 = 2^-9/(SH_X*SH_W)
#define ISC_DN 1.1920928955078125e-7f   // 2^-23 = 2^-9/(SH_H1*SH_W)

// ---------------- device scratch ----------------
__device__ int   g_cnt[NE];
__device__ int   g_fill[NE];
__device__ int   g_seg[NE];
__device__ int   g_tidx[NT * 2];
__device__ float g_tw[NT * 2];
__device__ int   g_btok[CAP];
__device__ float g_bw[CAP];

// bf16 hi planes + fp8 concat planes (2 bytes/elem each)
// f8 concat layout per row: groups of 16 elems -> 32 bytes:
//   A-role: [lo*SL (16B) | hi*SH (16B)],  B-role: [hi*SH | lo*SL]
__device__ uint16_t b_xh [(size_t)NT * HD];        __device__ uint8_t b_x8 [(size_t)NT * HD * 2];
__device__ uint16_t b_wgh[(size_t)NE * FF * HD];   __device__ uint8_t b_wg8[(size_t)NE * FF * HD * 2];
__device__ uint16_t b_wuh[(size_t)NE * FF * HD];   __device__ uint8_t b_wu8[(size_t)NE * FF * HD * 2];
__device__ uint16_t b_wdh[(size_t)NE * HD * FF];   __device__ uint8_t b_wd8[(size_t)NE * HD * FF * 2];
__device__ uint16_t b_sgh[(size_t)FSS * HD];       __device__ uint8_t b_sg8[(size_t)FSS * HD * 2];
__device__ uint16_t b_suh[(size_t)FSS * HD];       __device__ uint8_t b_su8[(size_t)FSS * HD * 2];
__device__ uint16_t b_sdh[(size_t)HD * FSS];       __device__ uint8_t b_sd8[(size_t)HD * FSS * 2];
__device__ uint16_t b_h1h[(size_t)CAP * FF];       __device__ uint8_t b_h18[(size_t)CAP * FF * 2];
__device__ uint16_t b_h1sh[(size_t)NT * FSS];      __device__ uint8_t b_h1s8[(size_t)NT * FSS * 2];

// ---------------- helpers ----------------
__device__ __forceinline__ uint32_t smem_u32(const void* p) {
    uint32_t a;
    asm("{ .reg .u64 t; cvta.to.shared.u64 t, %1; cvt.u32.u64 %0, t; }" : "=r"(a) : "l"(p));
    return a;
}
__device__ __forceinline__ void ldsm4(uint32_t* r, uint32_t addr) {
    asm volatile("ldmatrix.sync.aligned.m8n8.x4.shared.b16 {%0,%1,%2,%3}, [%4];"
        : "=r"(r[0]), "=r"(r[1]), "=r"(r[2]), "=r"(r[3]) : "r"(addr));
}
__device__ __forceinline__ void mma16816(float* c, const uint32_t* a, const uint32_t* b) {
    asm volatile(
        "mma.sync.aligned.m16n8k16.row.col.f32.bf16.bf16.f32 "
        "{%0,%1,%2,%3}, {%4,%5,%6,%7}, {%8,%9}, {%0,%1,%2,%3};"
        : "+f"(c[0]), "+f"(c[1]), "+f"(c[2]), "+f"(c[3])
        : "r"(a[0]), "r"(a[1]), "r"(a[2]), "r"(a[3]), "r"(b[0]), "r"(b[1]));
}
// fp8 correction MMA, zero C
__device__ __forceinline__ void qmma0(float* d, const uint32_t* a, const uint32_t* b) {
    asm volatile(
        "mma.sync.aligned.m16n8k32.row.col.f32.e4m3.e4m3.f32 "
        "{%0,%1,%2,%3}, {%4,%5,%6,%7}, {%8,%9}, {%10,%10,%10,%10};"
        : "=f"(d[0]), "=f"(d[1]), "=f"(d[2]), "=f"(d[3])
        : "r"(a[0]), "r"(a[1]), "r"(a[2]), "r"(a[3]),
          "r"(b[0]), "r"(b[1]), "f"(0.0f));
}
__device__ __forceinline__ void cp2(uint32_t dst, const void* src) {
    asm volatile(
        "cp.async.cg.shared.global [%0], [%1], 16;\n\t"
        "cp.async.cg.shared.global [%2], [%3], 16;"
        :: "r"(dst), "l"(src), "r"(dst + 16u), "l"((const char*)src + 16) : "memory");
}
__device__ __forceinline__ void cp_commit() {
    asm volatile("cp.async.commit_group;" ::: "memory");
}
template <int N> __device__ __forceinline__ void cp_wait() {
    asm volatile("cp.async.wait_group %0;" :: "n"(N) : "memory");
}

// ---------------- conversion kernel: fp32 -> bf16 hi + fp8 concat ----------------
__global__ void k_cvt2(const float* __restrict__ src, uint16_t* __restrict__ hi,
                       uint8_t* __restrict__ f8, int ngroups, int roleB, float sH) {
    int g = blockIdx.x * blockDim.x + threadIdx.x;
    if (g >= ngroups) return;
    float sL = sH * 512.f;
    const float4* s4 = (const float4*)src + (size_t)g * 4;
    uint32_t hw[8], lob[4], hib[4];
#pragma unroll
    for (int qd = 0; qd < 4; qd++) {
        float4 v = s4[qd];
        uint32_t h0, h1;
        asm("cvt.rn.bf16x2.f32 %0, %1, %2;" : "=r"(h0) : "f"(v.y), "f"(v.x));
        asm("cvt.rn.bf16x2.f32 %0, %1, %2;" : "=r"(h1) : "f"(v.w), "f"(v.z));
        hw[qd * 2] = h0; hw[qd * 2 + 1] = h1;
        float f0 = __uint_as_float(h0 << 16), f1 = __uint_as_float(h0 & 0xffff0000u);
        float f2 = __uint_as_float(h1 << 16), f3 = __uint_as_float(h1 & 0xffff0000u);
        float l0 = v.x - f0, l1 = v.y - f1, l2 = v.z - f2, l3 = v.w - f3;
        uint16_t pl0, pl1, ph0, ph1;
        asm("cvt.rn.satfinite.e4m3x2.f32 %0, %1, %2;" : "=h"(pl0) : "f"(l1 * sL), "f"(l0 * sL));
        asm("cvt.rn.satfinite.e4m3x2.f32 %0, %1, %2;" : "=h"(pl1) : "f"(l3 * sL), "f"(l2 * sL));
        asm("cvt.rn.satfinite.e4m3x2.f32 %0, %1, %2;" : "=h"(ph0) : "f"(f1 * sH), "f"(f0 * sH));
        asm("cvt.rn.satfinite.e4m3x2.f32 %0, %1, %2;" : "=h"(ph1) : "f"(f3 * sH), "f"(f2 * sH));
        lob[qd] = (uint32_t)pl0 | ((uint32_t)pl1 << 16);
        hib[qd] = (uint32_t)ph0 | ((uint32_t)ph1 << 16);
    }
    ((uint4*)hi)[(size_t)g * 2 + 0] = make_uint4(hw[0], hw[1], hw[2], hw[3]);
    ((uint4*)hi)[(size_t)g * 2 + 1] = make_uint4(hw[4], hw[5], hw[6], hw[7]);
    uint4 fl = make_uint4(lob[0], lob[1], lob[2], lob[3]);
    uint4 fh = make_uint4(hib[0], hib[1], hib[2], hib[3]);
    ((uint4*)f8)[(size_t)g * 2 + 0] = roleB ? fh : fl;
    ((uint4*)f8)[(size_t)g * 2 + 1] = roleB ? fl : fh;
}

// h1 epilogue split store: bf16 hi + fp8 A-role concat
__device__ __forceinline__ void h1_store2(uint16_t* hbuf, uint8_t* f8, int K,
                                          size_t row, int col, float o0, float o1,
                                          float sH, float sL) {
    uint32_t hp;
    asm("cvt.rn.bf16x2.f32 %0, %1, %2;" : "=r"(hp) : "f"(o1), "f"(o0));
    ((uint32_t*)hbuf)[(row * (size_t)K + col) >> 1] = hp;
    float f0 = __uint_as_float(hp << 16), f1 = __uint_as_float(hp & 0xffff0000u);
    float l0 = o0 - f0, l1 = o1 - f1;
    uint16_t lp, hq;
    asm("cvt.rn.satfinite.e4m3x2.f32 %0, %1, %2;" : "=h"(lp) : "f"(l1 * sL), "f"(l0 * sL));
    asm("cvt.rn.satfinite.e4m3x2.f32 %0, %1, %2;" : "=h"(hq) : "f"(f1 * sH), "f"(f0 * sH));
    size_t b = row * (size_t)(2 * K) + (size_t)(col >> 4) * 32 + (col & 15);
    *(uint16_t*)(f8 + b) = lp;
    *(uint16_t*)(f8 + b + 16) = hq;
}

// ---------------- gating ----------------
__global__ void k_init() {
    int i = threadIdx.x;
    if (i < NE) { g_cnt[i] = 0; g_fill[i] = 0; }
}

__global__ void k_gate(const float* __restrict__ x, const float* __restrict__ gw) {
    int gt = blockIdx.x * blockDim.x + threadIdx.x;
    int t = gt >> 5, lane = gt & 31;
    if (t >= NT) return;
    const float* xr = x + (size_t)t * HD;
    float acc[NE];
#pragma unroll
    for (int e = 0; e < NE; e++) acc[e] = 0.f;
    for (int i = lane; i < HD; i += 32) {
        float xv = xr[i];
#pragma unroll
        for (int e = 0; e < NE; e++) acc[e] += xv * gw[e * HD + i];
    }
#pragma unroll
    for (int e = 0; e < NE; e++)
#pragma unroll
        for (int o = 16; o > 0; o >>= 1)
            acc[e] += __shfl_down_sync(0xffffffffu, acc[e], o);
    if (lane == 0) {
        float m = acc[0];
#pragma unroll
        for (int e = 1; e < NE; e++) m = fmaxf(m, acc[e]);
        float p[NE], s = 0.f;
#pragma unroll
        for (int e = 0; e < NE; e++) { p[e] = expf(acc[e] - m); s += p[e]; }
        float inv = 1.f / s;
#pragma unroll
        for (int e = 0; e < NE; e++) p[e] *= inv;
        int i0 = 0; float v0 = p[0];
#pragma unroll
        for (int e = 1; e < NE; e++) if (p[e] > v0) { v0 = p[e]; i0 = e; }
        int i1 = -1; float v1 = -1.f;
#pragma unroll
        for (int e = 0; e < NE; e++) if (e != i0 && p[e] > v1) { v1 = p[e]; i1 = e; }
        float d = 1.f / (v0 + v1 + 1e-20f);
        g_tidx[t * 2 + 0] = i0; g_tw[t * 2 + 0] = v0 * d;
        g_tidx[t * 2 + 1] = i1; g_tw[t * 2 + 1] = v1 * d;
        atomicAdd(&g_cnt[i0], 1);
        atomicAdd(&g_cnt[i1], 1);
    }
}

__global__ void k_scan() {
    if (threadIdx.x == 0) {
        int acc = 0;
        for (int e = 0; e < NE; e++) {
            g_seg[e] = acc;
            acc += (g_cnt[e] + TMR - 1) / TMR * TMR;
        }
    }
}

__global__ void k_scatter() {
    int t = blockIdx.x * blockDim.x + threadIdx.x;
    if (t >= NT) return;
#pragma unroll
    for (int k = 0; k < 2; k++) {
        int e = g_tidx[t * 2 + k];
        float w = g_tw[t * 2 + k];
        int pos = atomicAdd(&g_fill[e], 1);
        g_btok[g_seg[e] + pos] = t;
        g_bw[g_seg[e] + pos] = w;
    }
}

__device__ __forceinline__ void find_expert(int row0, int& e_out, int& valid_out) {
    int e = -1, vr = 0;
    for (int i = 0; i < NE; i++) {
        int st = g_seg[i];
        int sz = (g_cnt[i] + TMR - 1) / TMR * TMR;
        if (row0 >= st && row0 < st + sz) { e = i; vr = g_cnt[i] - (row0 - st); break; }
    }
    e_out = e; valid_out = vr;
}

// ================= fused gate+up GEMM =================
// stage planes: Ah, A8, Gh, G8, Uh, U8 (each 128 rows x 80B)
template <int ROUTED>
__global__ __launch_bounds__(256, 1)
void k_upgate() {
    extern __shared__ char smem[];
    uint32_t sb0 = smem_u32(smem);
    uint32_t sb = (sb0 + 127u) & ~127u;
    char* ctrlp = smem + (sb - sb0) + 3 * STG_UP;
    int* sh_meta = (int*)ctrlp;
    int* stok = (int*)(ctrlp + 16);

    int tid = threadIdx.x, lane = tid & 31, wid = tid >> 5;
    int wm = wid & 1, wn = wid >> 1;
    int row0 = blockIdx.y * TMR, col0 = blockIdx.x * TMR;

    int e = 0, nvalid = TMR;
    if (ROUTED) {
        if (tid == 0) {
            int ee, vv; find_expert(row0, ee, vv);
            sh_meta[0] = ee; sh_meta[1] = vv;
        }
        __syncthreads();
        e = sh_meta[0];
        int v = sh_meta[1];
        if (e < 0 || v <= 0) return;
        nvalid = v > TMR ? TMR : v;
        if (tid < TMR) stok[tid] = (tid < nvalid) ? g_btok[row0 + tid] : 0;
        __syncthreads();
    }

    int frow = tid >> 1, q = tid & 1;
    uint32_t dof = (uint32_t)frow * ROWB + (uint32_t)q * 32u;

    const uint16_t *pah, *pgh, *puh;
    const uint8_t *pa8, *pg8, *pu8;
    if (ROUTED) {
        int tok = stok[frow];
        pah = b_xh + (size_t)tok * HD;
        pa8 = b_x8 + (size_t)tok * (HD * 2);
        size_t wo = (size_t)e * FF * HD + (size_t)(col0 + frow) * HD;
        pgh = b_wgh + wo; pg8 = b_wg8 + wo * 2;
        puh = b_wuh + wo; pu8 = b_wu8 + wo * 2;
    } else {
        pah = b_xh + (size_t)(row0 + frow) * HD;
        pa8 = b_x8 + (size_t)(row0 + frow) * (HD * 2);
        size_t wo = (size_t)(col0 + frow) * HD;
        pgh = b_sgh + wo; pg8 = b_sg8 + wo * 2;
        puh = b_suh + wo; pu8 = b_su8 + wo * 2;
    }

    auto fill = [&](int c) {
        int kh = c * KCH + q * 16;      // bf16 element offset
        int k8 = c * 64 + q * 32;       // f8 byte offset (2 groups of 32B per chunk)
        uint32_t sg = sb + (uint32_t)(c % 3) * STG_UP + dof;
        cp2(sg + 0u * PL, pah + kh);
        cp2(sg + 1u * PL, pa8 + k8);
        cp2(sg + 2u * PL, pgh + kh);
        cp2(sg + 3u * PL, pg8 + k8);
        cp2(sg + 4u * PL, puh + kh);
        cp2(sg + 5u * PL, pu8 + k8);
    };

    uint32_t a_off = (uint32_t)(wm * 64 + (lane & 15)) * ROWB + (uint32_t)((lane >> 4) * 16);
    uint32_t b_off = (uint32_t)(wn * 32 + ((lane >> 4) * 8) + (lane & 7)) * ROWB
                   + (uint32_t)(((lane >> 3) & 1) * 16);

    float accg[4][4][4], accu[4][4][4];
#pragma unroll
    for (int i = 0; i < 4; i++)
#pragma unroll
        for (int j = 0; j < 4; j++)
#pragma unroll
            for (int p = 0; p < 4; p++) { accg[i][j][p] = 0.f; accu[i][j][p] = 0.f; }

    const int NC = HD / KCH;
    fill(0); cp_commit();
    fill(1); cp_commit();

    for (int c = 0; c < NC; c++) {
        cp_wait<1>();
        __syncthreads();
        if (c + 2 < NC) fill(c + 2);
        cp_commit();
        uint32_t sg = sb + (uint32_t)(c % 3) * STG_UP;
#pragma unroll
        for (int s = 0; s < 2; s++) {
            uint32_t ka = a_off + (uint32_t)s * 32u;
            uint32_t kb = b_off + (uint32_t)s * 32u;
            uint32_t ah[4][4], a8[4][4];
#pragma unroll
            for (int i = 0; i < 4; i++) {
                uint32_t o = (uint32_t)i * (16u * ROWB);
                ldsm4(ah[i], sg + 0u * PL + ka + o);
                ldsm4(a8[i], sg + 1u * PL + ka + o);
            }
            uint32_t bh[2][4], b8[2][4];
#pragma unroll
            for (int jj = 0; jj < 2; jj++) {
                uint32_t o = (uint32_t)jj * (16u * ROWB);
                ldsm4(bh[jj], sg + 2u * PL + kb + o);
                ldsm4(b8[jj], sg + 3u * PL + kb + o);
            }
#pragma unroll
            for (int i = 0; i < 4; i++)
#pragma unroll
                for (int j = 0; j < 4; j++) {
                    mma16816(accg[i][j], ah[i], &bh[j >> 1][(j & 1) * 2]);
                    float t[4];
                    qmma0(t, a8[i], &b8[j >> 1][(j & 1) * 2]);
#pragma unroll
                    for (int p = 0; p < 4; p++)
                        accg[i][j][p] = fmaf(t[p], ISC_UP, accg[i][j][p]);
                }
#pragma unroll
            for (int jj = 0; jj < 2; jj++) {
                uint32_t o = (uint32_t)jj * (16u * ROWB);
                ldsm4(bh[jj], sg + 4u * PL + kb + o);
                ldsm4(b8[jj], sg + 5u * PL + kb + o);
            }
#pragma unroll
            for (int i = 0; i < 4; i++)
#pragma unroll
                for (int j = 0; j < 4; j++) {
                    mma16816(accu[i][j], ah[i], &bh[j >> 1][(j & 1) * 2]);
                    float t[4];
                    qmma0(t, a8[i], &b8[j >> 1][(j & 1) * 2]);
#pragma unroll
                    for (int p = 0; p < 4; p++)
                        accu[i][j][p] = fmaf(t[p], ISC_UP, accu[i][j][p]);
                }
        }
    }

    // epilogue: silu(g)*u -> bf16 hi + fp8 concat h1
    const int LDC = ROUTED ? FF : FSS;
    uint16_t* dh = ROUTED ? b_h1h : b_h1sh;
    uint8_t*  d8 = ROUTED ? b_h18 : b_h1s8;
#pragma unroll
    for (int i = 0; i < 4; i++) {
        int rl0 = wm * 64 + i * 16 + (lane >> 2);
        int rl1 = rl0 + 8;
#pragma unroll
        for (int j = 0; j < 4; j++) {
            int cl = wn * 32 + j * 8 + (lane & 3) * 2;
            if (!ROUTED || rl0 < nvalid) {
                float g0 = accg[i][j][0], g1 = accg[i][j][1];
                float o0 = g0 / (1.f + __expf(-g0)) * accu[i][j][0];
                float o1 = g1 / (1.f + __expf(-g1)) * accu[i][j][1];
                h1_store2(dh, d8, LDC, (size_t)(row0 + rl0), col0 + cl, o0, o1, SH_H1, SL_H1);
            }
            if (!ROUTED || rl1 < nvalid) {
                float g0 = accg[i][j][2], g1 = accg[i][j][3];
                float o0 = g0 / (1.f + __expf(-g0)) * accu[i][j][2];
                float o1 = g1 / (1.f + __expf(-g1)) * accu[i][j][3];
                h1_store2(dh, d8, LDC, (size_t)(row0 + rl1), col0 + cl, o0, o1, SH_H1, SL_H1);
            }
        }
    }
}

// ================= down GEMM =================
// stage planes: Ah, A8, Bh, B8
template <int ROUTED>
__global__ __launch_bounds__(256, 1)
void k_down(float* __restrict__ out) {
    extern __shared__ char smem[];
    uint32_t sb0 = smem_u32(smem);
    uint32_t sb = (sb0 + 127u) & ~127u;
    char* ctrlp = smem + (sb - sb0) + 3 * STG_DN;
    int* sh_meta = (int*)ctrlp;
    int* stok = (int*)(ctrlp + 16);
    float* swt = (float*)(ctrlp + 16 + 512);

    int tid = threadIdx.x, lane = tid & 31, wid = tid >> 5;
    int wm = wid & 1, wn = wid >> 1;
    int row0 = blockIdx.y * TMR, col0 = blockIdx.x * TMR;

    int e = 0, nvalid = TMR;
    if (ROUTED) {
        if (tid == 0) {
            int ee, vv; find_expert(row0, ee, vv);
            sh_meta[0] = ee; sh_meta[1] = vv;
        }
        __syncthreads();
        e = sh_meta[0];
        int v = sh_meta[1];
        if (e < 0 || v <= 0) return;
        nvalid = v > TMR ? TMR : v;
        if (tid < TMR) {
            bool ok = tid < nvalid;
            stok[tid] = ok ? g_btok[row0 + tid] : 0;
            swt[tid]  = ok ? g_bw[row0 + tid]   : 0.f;
        }
        __syncthreads();
    }

    const int KD = ROUTED ? FF : FSS;
    int frow = tid >> 1, q = tid & 1;
    uint32_t dof = (uint32_t)frow * ROWB + (uint32_t)q * 32u;

    const uint16_t* pah = (ROUTED ? b_h1h : b_h1sh) + (size_t)(row0 + frow) * KD;
    const uint8_t*  pa8 = (ROUTED ? b_h18 : b_h1s8) + (size_t)(row0 + frow) * (KD * 2);
    const uint16_t* pbh = (ROUTED ? b_wdh + (size_t)e * HD * FF : b_sdh)
                          + (size_t)(col0 + frow) * KD;
    const uint8_t*  pb8 = (ROUTED ? b_wd8 + (size_t)e * HD * FF * 2 : b_sd8)
                          + (size_t)(col0 + frow) * (KD * 2);

    auto fill = [&](int c) {
        int kh = c * KCH + q * 16;
        int k8 = c * 64 + q * 32;
        uint32_t sg = sb + (uint32_t)(c % 3) * STG_DN + dof;
        cp2(sg + 0u * PL, pah + kh);
        cp2(sg + 1u * PL, pa8 + k8);
        cp2(sg + 2u * PL, pbh + kh);
        cp2(sg + 3u * PL, pb8 + k8);
    };

    uint32_t a_off = (uint32_t)(wm * 64 + (lane & 15)) * ROWB + (uint32_t)((lane >> 4) * 16);
    uint32_t b_off = (uint32_t)(wn * 32 + ((lane >> 4) * 8) + (lane & 7)) * ROWB
                   + (uint32_t)(((lane >> 3) & 1) * 16);

    float acc[4][4][4];
#pragma unroll
    for (int i = 0; i < 4; i++)
#pragma unroll
        for (int j = 0; j < 4; j++)
#pragma unroll
            for (int p = 0; p < 4; p++) acc[i][j][p] = 0.f;

    const int NC = KD / KCH;
    fill(0); cp_commit();
    fill(1); cp_commit();

    for (int c = 0; c < NC; c++) {
        cp_wait<1>();
        __syncthreads();
        if (c + 2 < NC) fill(c + 2);
        cp_commit();
        uint32_t sg = sb + (uint32_t)(c % 3) * STG_DN;
#pragma unroll
        for (int s = 0; s < 2; s++) {
            uint32_t ka = a_off + (uint32_t)s * 32u;
            uint32_t kb = b_off + (uint32_t)s * 32u;
            uint32_t ah[4][4], a8[4][4];
#pragma unroll
            for (int i = 0; i < 4; i++) {
                uint32_t o = (uint32_t)i * (16u * ROWB);
                ldsm4(ah[i], sg + 0u * PL + ka + o);
                ldsm4(a8[i], sg + 1u * PL + ka + o);
            }
            uint32_t bh[2][4], b8[2][4];
#pragma unroll
            for (int jj = 0; jj < 2; jj++) {
                uint32_t o = (uint32_t)jj * (16u * ROWB);
                ldsm4(bh[jj], sg + 2u * PL + kb + o);
                ldsm4(b8[jj], sg + 3u * PL + kb + o);
            }
#pragma unroll
            for (int i = 0; i < 4; i++)
#pragma unroll
                for (int j = 0; j < 4; j++) {
                    mma16816(acc[i][j], ah[i], &bh[j >> 1][(j & 1) * 2]);
                    float t[4];
                    qmma0(t, a8[i], &b8[j >> 1][(j & 1) * 2]);
#pragma unroll
                    for (int p = 0; p < 4; p++)
                        acc[i][j][p] = fmaf(t[p], ISC_DN, acc[i][j][p]);
                }
        }
    }

    // epilogue
#pragma unroll
    for (int i = 0; i < 4; i++) {
        int rl0 = wm * 64 + i * 16 + (lane >> 2);
        int rl1 = rl0 + 8;
#pragma unroll
        for (int j = 0; j < 4; j++) {
            int cl = wn * 32 + j * 8 + (lane & 3) * 2;
            if (ROUTED) {
                if (rl0 < nvalid) {
                    float w = swt[rl0];
                    float* o = out + (size_t)stok[rl0] * HD + col0 + cl;
                    atomicAdd(&o[0], w * acc[i][j][0]);
                    atomicAdd(&o[1], w * acc[i][j][1]);
                }
                if (rl1 < nvalid) {
                    float w = swt[rl1];
                    float* o = out + (size_t)stok[rl1] * HD + col0 + cl;
                    atomicAdd(&o[0], w * acc[i][j][2]);
                    atomicAdd(&o[1], w * acc[i][j][3]);
                }
            } else {
                float2 v0; v0.x = acc[i][j][0]; v0.y = acc[i][j][1];
                float2 v1; v1.x = acc[i][j][2]; v1.y = acc[i][j][3];
                *(float2*)(out + (size_t)(row0 + rl0) * HD + col0 + cl) = v0;
                *(float2*)(out + (size_t)(row0 + rl1) * HD + col0 + cl) = v1;
            }
        }
    }
}

// ---------------- launch ----------------
extern "C" void kernel_launch(void* const* d_in, const int* in_sizes, int n_in,
                              void* d_out, int out_size) {
    const float* x   = (const float*)d_in[0];
    const float* gw  = (const float*)d_in[1];
    const float* wg  = (const float*)d_in[2];
    const float* wu  = (const float*)d_in[3];
    const float* wd  = (const float*)d_in[4];
    const float* swg = (const float*)d_in[5];
    const float* swu = (const float*)d_in[6];
    const float* swd = (const float*)d_in[7];
    float* out = (float*)d_out;

    cudaFuncSetAttribute(k_upgate<1>, cudaFuncAttributeMaxDynamicSharedMemorySize, UP_SMEM);
    cudaFuncSetAttribute(k_upgate<0>, cudaFuncAttributeMaxDynamicSharedMemorySize, UP_SMEM);
    cudaFuncSetAttribute(k_down<1>,   cudaFuncAttributeMaxDynamicSharedMemorySize, DN_SMEM);
    cudaFuncSetAttribute(k_down<0>,   cudaFuncAttributeMaxDynamicSharedMemorySize, DN_SMEM);

    k_init<<<1, 32>>>();
    k_gate<<<NT / 8, 256>>>(x, gw);
    k_scan<<<1, 32>>>();
    k_scatter<<<(NT + 255) / 256, 256>>>();

    // pre-convert: bf16 hi + fp8 concat
    {
        uint16_t *hx;  uint8_t *f8x;
        // x (A-role)
        int ng = NT * HD / 16;
        cudaGetSymbolAddress((void**)&hx, b_xh); cudaGetSymbolAddress((void**)&f8x, b_x8);
        k_cvt2<<<(ng + 255) / 256, 256>>>(x, hx, f8x, ng, 0, SH_X);
        // routed weights (B-role)
        ng = NE * FF * HD / 16;
        cudaGetSymbolAddress((void**)&hx, b_wgh); cudaGetSymbolAddress((void**)&f8x, b_wg8);
        k_cvt2<<<(ng + 255) / 256, 256>>>(wg, hx, f8x, ng, 1, SH_W);
        cudaGetSymbolAddress((void**)&hx, b_wuh); cudaGetSymbolAddress((void**)&f8x, b_wu8);
        k_cvt2<<<(ng + 255) / 256, 256>>>(wu, hx, f8x, ng, 1, SH_W);
        cudaGetSymbolAddress((void**)&hx, b_wdh); cudaGetSymbolAddress((void**)&f8x, b_wd8);
        k_cvt2<<<(ng + 255) / 256, 256>>>(wd, hx, f8x, ng, 1, SH_W);
        // shared weights (B-role)
        ng = FSS * HD / 16;
        cudaGetSymbolAddress((void**)&hx, b_sgh); cudaGetSymbolAddress((void**)&f8x, b_sg8);
        k_cvt2<<<(ng + 255) / 256, 256>>>(swg, hx, f8x, ng, 1, SH_W);
        cudaGetSymbolAddress((void**)&hx, b_suh); cudaGetSymbolAddress((void**)&f8x, b_su8);
        k_cvt2<<<(ng + 255) / 256, 256>>>(swu, hx, f8x, ng, 1, SH_W);
        cudaGetSymbolAddress((void**)&hx, b_sdh); cudaGetSymbolAddress((void**)&f8x, b_sd8);
        k_cvt2<<<(ng + 255) / 256, 256>>>(swd, hx, f8x, ng, 1, SH_W);
    }

    // shared expert first: its down-proj initializes `out` with plain stores
    k_upgate<0><<<dim3(FSS / TMR, NT / TMR), 256, UP_SMEM>>>();
    k_down<0><<<dim3(HD / TMR, NT / TMR), 256, DN_SMEM>>>(out);

    // routed experts accumulate on top via atomicAdd
    k_upgate<1><<<dim3(FF / TMR, CAPTILES), 256, UP_SMEM>>>();
    k_down<1><<<dim3(HD / TMR, CAPTILES), 256, DN_SMEM>>>(out);
}

// round 13
// speedup vs baseline: 1.3543x; 1.3543x over previous
#include <cuda_runtime.h>
#include <cstdint>

// ---------------- problem constants ----------------
#define NT   2048
#define HD   2048
#define NE   8
#define FF   1408
#define FSS  2816
#define TMR  128
#define CAPTILES 40
#define CAP (CAPTILES * TMR)

#define KCH   32           // K elements per pipeline stage
#define ROWB  80u          // padded smem row bytes (64B data + 16B pad)
#define PL    10240u       // plane bytes = 128 rows * 80B
#define STG_UP (6u * PL)
#define STG_DN (4u * PL)
#define UP_SMEM (3 * 61440 + 4096)
#define DN_SMEM (3 * 40960 + 4096)

// fused grid decode
#define UP_SH_TILES (16 * 22)     // 352: NT/128 x FSS/128
#define UP_ALL      (UP_SH_TILES + CAPTILES * 11)   // + 40 x FF/128 = 792
#define DN_SH_TILES (16 * 16)     // 256: NT/128 x HD/128
#define DN_ALL      (DN_SH_TILES + CAPTILES * 16)   // + 40 x HD/128 = 896

// ---------------- device scratch ----------------
__device__ int   g_cnt[NE];
__device__ int   g_fill[NE];
__device__ int   g_seg[NE];
__device__ int   g_tidx[NT * 2];
__device__ float g_tw[NT * 2];
__device__ int   g_btok[CAP];
__device__ float g_bw[CAP];

// bf16 hi/lo planes (pre-converted every launch; deterministic)
__device__ uint16_t b_xh[(size_t)NT * HD],   b_xl[(size_t)NT * HD];
__device__ uint16_t b_wgh[(size_t)NE * FF * HD], b_wgl[(size_t)NE * FF * HD];
__device__ uint16_t b_wuh[(size_t)NE * FF * HD], b_wul[(size_t)NE * FF * HD];
__device__ uint16_t b_wdh[(size_t)NE * HD * FF], b_wdl[(size_t)NE * HD * FF];
__device__ uint16_t b_sgh[(size_t)FSS * HD], b_sgl[(size_t)FSS * HD];
__device__ uint16_t b_suh[(size_t)FSS * HD], b_sul[(size_t)FSS * HD];
__device__ uint16_t b_sdh[(size_t)HD * FSS], b_sdl[(size_t)HD * FSS];
__device__ uint16_t b_h1h[(size_t)CAP * FF], b_h1l[(size_t)CAP * FF];
__device__ uint16_t b_h1sh[(size_t)NT * FSS], b_h1sl[(size_t)NT * FSS];

// ---------------- helpers ----------------
__device__ __forceinline__ uint32_t smem_u32(const void* p) {
    uint32_t a;
    asm("{ .reg .u64 t; cvta.to.shared.u64 t, %1; cvt.u32.u64 %0, t; }" : "=r"(a) : "l"(p));
    return a;
}
__device__ __forceinline__ void ldsm4(uint32_t* r, uint32_t addr) {
    asm volatile("ldmatrix.sync.aligned.m8n8.x4.shared.b16 {%0,%1,%2,%3}, [%4];"
        : "=r"(r[0]), "=r"(r[1]), "=r"(r[2]), "=r"(r[3]) : "r"(addr));
}
__device__ __forceinline__ void mma16816(float* c, const uint32_t* a, const uint32_t* b) {
    asm volatile(
        "mma.sync.aligned.m16n8k16.row.col.f32.bf16.bf16.f32 "
        "{%0,%1,%2,%3}, {%4,%5,%6,%7}, {%8,%9}, {%0,%1,%2,%3};"
        : "+f"(c[0]), "+f"(c[1]), "+f"(c[2]), "+f"(c[3])
        : "r"(a[0]), "r"(a[1]), "r"(a[2]), "r"(a[3]), "r"(b[0]), "r"(b[1]));
}
__device__ __forceinline__ void cp2(uint32_t dst, const void* src) {
    asm volatile(
        "cp.async.cg.shared.global [%0], [%1], 16;\n\t"
        "cp.async.cg.shared.global [%2], [%3], 16;"
        :: "r"(dst), "l"(src), "r"(dst + 16u), "l"((const char*)src + 16) : "memory");
}
__device__ __forceinline__ void cp_commit() {
    asm volatile("cp.async.commit_group;" ::: "memory");
}
template <int N> __device__ __forceinline__ void cp_wait() {
    asm volatile("cp.async.wait_group %0;" :: "n"(N) : "memory");
}
// split fp32 pair -> bf16x2 hi + bf16x2 lo, store 4B each
__device__ __forceinline__ void split_store(uint16_t* hi, uint16_t* lo, size_t idx2,
                                            float o0, float o1) {
    uint32_t hp, lp;
    asm("cvt.rn.bf16x2.f32 %0, %1, %2;" : "=r"(hp) : "f"(o1), "f"(o0));
    float r0 = o0 - __uint_as_float(hp << 16);
    float r1 = o1 - __uint_as_float(hp & 0xffff0000u);
    asm("cvt.rn.bf16x2.f32 %0, %1, %2;" : "=r"(lp) : "f"(r1), "f"(r0));
    ((uint32_t*)hi)[idx2] = hp;
    ((uint32_t*)lo)[idx2] = lp;
}

// ---------------- conversion kernel (fp32 -> bf16 hi/lo) ----------------
__global__ void k_cvt(const float* __restrict__ src, int which, int n4) {
    int i = blockIdx.x * blockDim.x + threadIdx.x;
    if (i >= n4) return;
    uint16_t *hi, *lo;
    switch (which) {
        case 0: hi = b_xh;  lo = b_xl;  break;
        case 1: hi = b_wgh; lo = b_wgl; break;
        case 2: hi = b_wuh; lo = b_wul; break;
        case 3: hi = b_wdh; lo = b_wdl; break;
        case 4: hi = b_sgh; lo = b_sgl; break;
        case 5: hi = b_suh; lo = b_sul; break;
        default: hi = b_sdh; lo = b_sdl; break;
    }
    float4 v = ((const float4*)src)[i];
    uint32_t h0, h1, l0, l1;
    asm("cvt.rn.bf16x2.f32 %0, %1, %2;" : "=r"(h0) : "f"(v.y), "f"(v.x));
    asm("cvt.rn.bf16x2.f32 %0, %1, %2;" : "=r"(h1) : "f"(v.w), "f"(v.z));
    float r0 = v.x - __uint_as_float(h0 << 16);
    float r1 = v.y - __uint_as_float(h0 & 0xffff0000u);
    float r2 = v.z - __uint_as_float(h1 << 16);
    float r3 = v.w - __uint_as_float(h1 & 0xffff0000u);
    asm("cvt.rn.bf16x2.f32 %0, %1, %2;" : "=r"(l0) : "f"(r1), "f"(r0));
    asm("cvt.rn.bf16x2.f32 %0, %1, %2;" : "=r"(l1) : "f"(r3), "f"(r2));
    uint2 hv; hv.x = h0; hv.y = h1;
    uint2 lv; lv.x = l0; lv.y = l1;
    ((uint2*)hi)[i] = hv;
    ((uint2*)lo)[i] = lv;
}

// ---------------- zero out ----------------
__global__ void k_zero(float4* __restrict__ o, int n4) {
    int i = blockIdx.x * blockDim.x + threadIdx.x;
    if (i < n4) o[i] = make_float4(0.f, 0.f, 0.f, 0.f);
}

// ---------------- gating ----------------
__global__ void k_init() {
    int i = threadIdx.x;
    if (i < NE) { g_cnt[i] = 0; g_fill[i] = 0; }
}

__global__ void k_gate(const float* __restrict__ x, const float* __restrict__ gw) {
    int gt = blockIdx.x * blockDim.x + threadIdx.x;
    int t = gt >> 5, lane = gt & 31;
    if (t >= NT) return;
    const float* xr = x + (size_t)t * HD;
    float acc[NE];
#pragma unroll
    for (int e = 0; e < NE; e++) acc[e] = 0.f;
    for (int i = lane; i < HD; i += 32) {
        float xv = xr[i];
#pragma unroll
        for (int e = 0; e < NE; e++) acc[e] += xv * gw[e * HD + i];
    }
#pragma unroll
    for (int e = 0; e < NE; e++)
#pragma unroll
        for (int o = 16; o > 0; o >>= 1)
            acc[e] += __shfl_down_sync(0xffffffffu, acc[e], o);
    if (lane == 0) {
        float m = acc[0];
#pragma unroll
        for (int e = 1; e < NE; e++) m = fmaxf(m, acc[e]);
        float p[NE], s = 0.f;
#pragma unroll
        for (int e = 0; e < NE; e++) { p[e] = expf(acc[e] - m); s += p[e]; }
        float inv = 1.f / s;
#pragma unroll
        for (int e = 0; e < NE; e++) p[e] *= inv;
        int i0 = 0; float v0 = p[0];
#pragma unroll
        for (int e = 1; e < NE; e++) if (p[e] > v0) { v0 = p[e]; i0 = e; }
        int i1 = -1; float v1 = -1.f;
#pragma unroll
        for (int e = 0; e < NE; e++) if (e != i0 && p[e] > v1) { v1 = p[e]; i1 = e; }
        float d = 1.f / (v0 + v1 + 1e-20f);
        g_tidx[t * 2 + 0] = i0; g_tw[t * 2 + 0] = v0 * d;
        g_tidx[t * 2 + 1] = i1; g_tw[t * 2 + 1] = v1 * d;
        atomicAdd(&g_cnt[i0], 1);
        atomicAdd(&g_cnt[i1], 1);
    }
}

__global__ void k_scan() {
    if (threadIdx.x == 0) {
        int acc = 0;
        for (int e = 0; e < NE; e++) {
            g_seg[e] = acc;
            acc += (g_cnt[e] + TMR - 1) / TMR * TMR;
        }
    }
}

__global__ void k_scatter() {
    int t = blockIdx.x * blockDim.x + threadIdx.x;
    if (t >= NT) return;
#pragma unroll
    for (int k = 0; k < 2; k++) {
        int e = g_tidx[t * 2 + k];
        float w = g_tw[t * 2 + k];
        int pos = atomicAdd(&g_fill[e], 1);
        g_btok[g_seg[e] + pos] = t;
        g_bw[g_seg[e] + pos] = w;
    }
}

__device__ __forceinline__ void find_expert(int row0, int& e_out, int& valid_out) {
    int e = -1, vr = 0;
    for (int i = 0; i < NE; i++) {
        int st = g_seg[i];
        int sz = (g_cnt[i] + TMR - 1) / TMR * TMR;
        if (row0 >= st && row0 < st + sz) { e = i; vr = g_cnt[i] - (row0 - st); break; }
    }
    e_out = e; valid_out = vr;
}

// ================= fused gate+up GEMM (shared + routed in one launch) =================
// stage planes: Ah, Al, Gh, Gl, Uh, Ul; rows padded to 80B
__global__ __launch_bounds__(256, 1)
void k_up_all() {
    extern __shared__ char smem[];
    uint32_t sb0 = smem_u32(smem);
    uint32_t sb = (sb0 + 127u) & ~127u;
    char* ctrlp = smem + (sb - sb0) + 3 * STG_UP;
    int* sh_meta = (int*)ctrlp;
    int* stok = (int*)(ctrlp + 16);

    int tid = threadIdx.x, lane = tid & 31, wid = tid >> 5;
    int wm = wid & 1, wn = wid >> 1;

    int bid = blockIdx.x;
    int routed, row0, col0;
    if (bid < UP_SH_TILES) {
        routed = 0;
        row0 = (bid / 22) * TMR;
        col0 = (bid % 22) * TMR;
    } else {
        routed = 1;
        int r = bid - UP_SH_TILES;
        row0 = (r / 11) * TMR;
        col0 = (r % 11) * TMR;
    }

    int e = 0, nvalid = TMR;
    if (routed) {
        if (tid == 0) {
            int ee, vv; find_expert(row0, ee, vv);
            sh_meta[0] = ee; sh_meta[1] = vv;
        }
        __syncthreads();
        e = sh_meta[0];
        int v = sh_meta[1];
        if (e < 0 || v <= 0) return;
        nvalid = v > TMR ? TMR : v;
        if (tid < TMR) stok[tid] = (tid < nvalid) ? g_btok[row0 + tid] : 0;
        __syncthreads();
    }

    // fill mapping: thread owns (row = tid>>1, 16-elem half q = tid&1)
    int frow = tid >> 1, q = tid & 1;
    uint32_t dof = (uint32_t)frow * ROWB + (uint32_t)q * 32u;

    const uint16_t *pah, *pal, *pgh, *pgl, *puh, *pul;
    if (routed) {
        int tok = stok[frow];
        pah = b_xh + (size_t)tok * HD; pal = b_xl + (size_t)tok * HD;
        size_t wo = (size_t)e * FF * HD + (size_t)(col0 + frow) * HD;
        pgh = b_wgh + wo; pgl = b_wgl + wo;
        puh = b_wuh + wo; pul = b_wul + wo;
    } else {
        pah = b_xh + (size_t)(row0 + frow) * HD; pal = b_xl + (size_t)(row0 + frow) * HD;
        size_t wo = (size_t)(col0 + frow) * HD;
        pgh = b_sgh + wo; pgl = b_sgl + wo;
        puh = b_suh + wo; pul = b_sul + wo;
    }

    auto fill = [&](int c) {
        int k = c * KCH + q * 16;
        uint32_t sg = sb + (uint32_t)(c % 3) * STG_UP + dof;
        cp2(sg + 0u * PL, pah + k);
        cp2(sg + 1u * PL, pal + k);
        cp2(sg + 2u * PL, pgh + k);
        cp2(sg + 3u * PL, pgl + k);
        cp2(sg + 4u * PL, puh + k);
        cp2(sg + 5u * PL, pul + k);
    };

    uint32_t a_off = (uint32_t)(wm * 64 + (lane & 15)) * ROWB + (uint32_t)((lane >> 4) * 16);
    uint32_t b_off = (uint32_t)(wn * 32 + ((lane >> 4) * 8) + (lane & 7)) * ROWB
                   + (uint32_t)(((lane >> 3) & 1) * 16);

    float accg[4][4][4], accu[4][4][4];
#pragma unroll
    for (int i = 0; i < 4; i++)
#pragma unroll
        for (int j = 0; j < 4; j++)
#pragma unroll
            for (int p = 0; p < 4; p++) { accg[i][j][p] = 0.f; accu[i][j][p] = 0.f; }

    const int NC = HD / KCH;
    fill(0); cp_commit();
    fill(1); cp_commit();

    for (int c = 0; c < NC; c++) {
        cp_wait<1>();
        __syncthreads();
        if (c + 2 < NC) fill(c + 2);
        cp_commit();
        uint32_t sg = sb + (uint32_t)(c % 3) * STG_UP;
#pragma unroll
        for (int s = 0; s < 2; s++) {
            uint32_t ka = a_off + (uint32_t)s * 32u;
            uint32_t kb = b_off + (uint32_t)s * 32u;
            // issue ALL ldsm for this s up-front so latency hides under MMAs
            uint32_t ah[4][4], al[4][4];
#pragma unroll
            for (int i = 0; i < 4; i++) {
                uint32_t o = ka + (uint32_t)i * (16u * ROWB);
                ldsm4(ah[i], sg + 0u * PL + o);
                ldsm4(al[i], sg + 1u * PL + o);
            }
            uint32_t bgh[2][4], bgl[2][4], buh[2][4], bul[2][4];
#pragma unroll
            for (int jj = 0; jj < 2; jj++) {
                uint32_t o = kb + (uint32_t)jj * (16u * ROWB);
                ldsm4(bgh[jj], sg + 2u * PL + o);
                ldsm4(bgl[jj], sg + 3u * PL + o);
                ldsm4(buh[jj], sg + 4u * PL + o);
                ldsm4(bul[jj], sg + 5u * PL + o);
            }
#pragma unroll
            for (int i = 0; i < 4; i++)
#pragma unroll
                for (int j = 0; j < 4; j++) {
                    const uint32_t* fh = &bgh[j >> 1][(j & 1) * 2];
                    const uint32_t* fl = &bgl[j >> 1][(j & 1) * 2];
                    mma16816(accg[i][j], ah[i], fh);
                    mma16816(accg[i][j], al[i], fh);
                    mma16816(accg[i][j], ah[i], fl);
                }
#pragma unroll
            for (int i = 0; i < 4; i++)
#pragma unroll
                for (int j = 0; j < 4; j++) {
                    const uint32_t* fh = &buh[j >> 1][(j & 1) * 2];
                    const uint32_t* fl = &bul[j >> 1][(j & 1) * 2];
                    mma16816(accu[i][j], ah[i], fh);
                    mma16816(accu[i][j], al[i], fh);
                    mma16816(accu[i][j], ah[i], fl);
                }
        }
    }

    // epilogue: silu(g)*u -> bf16 hi/lo h1
    const int LDC = routed ? FF : FSS;
    uint16_t* dh = routed ? b_h1h : b_h1sh;
    uint16_t* dl = routed ? b_h1l : b_h1sl;
#pragma unroll
    for (int i = 0; i < 4; i++) {
        int rl0 = wm * 64 + i * 16 + (lane >> 2);
        int rl1 = rl0 + 8;
#pragma unroll
        for (int j = 0; j < 4; j++) {
            int cl = wn * 32 + j * 8 + (lane & 3) * 2;
            if (!routed || rl0 < nvalid) {
                float g0 = accg[i][j][0], g1 = accg[i][j][1];
                float o0 = g0 / (1.f + __expf(-g0)) * accu[i][j][0];
                float o1 = g1 / (1.f + __expf(-g1)) * accu[i][j][1];
                split_store(dh, dl, ((size_t)(row0 + rl0) * LDC + col0 + cl) >> 1, o0, o1);
            }
            if (!routed || rl1 < nvalid) {
                float g0 = accg[i][j][2], g1 = accg[i][j][3];
                float o0 = g0 / (1.f + __expf(-g0)) * accu[i][j][2];
                float o1 = g1 / (1.f + __expf(-g1)) * accu[i][j][3];
                split_store(dh, dl, ((size_t)(row0 + rl1) * LDC + col0 + cl) >> 1, o0, o1);
            }
        }
    }
}

// ================= fused down GEMM (shared + routed, all-atomic epilogue) =================
// stage planes: Ah, Al, Bh, Bl
__global__ __launch_bounds__(256, 1)
void k_dn_all(float* __restrict__ out) {
    extern __shared__ char smem[];
    uint32_t sb0 = smem_u32(smem);
    uint32_t sb = (sb0 + 127u) & ~127u;
    char* ctrlp = smem + (sb - sb0) + 3 * STG_DN;
    int* sh_meta = (int*)ctrlp;
    int* stok = (int*)(ctrlp + 16);
    float* swt = (float*)(ctrlp + 16 + 512);

    int tid = threadIdx.x, lane = tid & 31, wid = tid >> 5;
    int wm = wid & 1, wn = wid >> 1;

    int bid = blockIdx.x;
    int routed, row0, col0;
    if (bid < DN_SH_TILES) {
        routed = 0;
        row0 = (bid / 16) * TMR;
        col0 = (bid % 16) * TMR;
    } else {
        routed = 1;
        int r = bid - DN_SH_TILES;
        row0 = (r / 16) * TMR;
        col0 = (r % 16) * TMR;
    }

    int e = 0, nvalid = TMR;
    if (routed) {
        if (tid == 0) {
            int ee, vv; find_expert(row0, ee, vv);
            sh_meta[0] = ee; sh_meta[1] = vv;
        }
        __syncthreads();
        e = sh_meta[0];
        int v = sh_meta[1];
        if (e < 0 || v <= 0) return;
        nvalid = v > TMR ? TMR : v;
        if (tid < TMR) {
            bool ok = tid < nvalid;
            stok[tid] = ok ? g_btok[row0 + tid] : 0;
            swt[tid]  = ok ? g_bw[row0 + tid]   : 0.f;
        }
        __syncthreads();
    }

    const int KD = routed ? FF : FSS;
    int frow = tid >> 1, q = tid & 1;
    uint32_t dof = (uint32_t)frow * ROWB + (uint32_t)q * 32u;

    const uint16_t* pah = (routed ? b_h1h : b_h1sh) + (size_t)(row0 + frow) * KD;
    const uint16_t* pal = (routed ? b_h1l : b_h1sl) + (size_t)(row0 + frow) * KD;
    const uint16_t* pbh = (routed ? b_wdh + (size_t)e * HD * FF : b_sdh)
                          + (size_t)(col0 + frow) * KD;
    const uint16_t* pbl = (routed ? b_wdl + (size_t)e * HD * FF : b_sdl)
                          + (size_t)(col0 + frow) * KD;

    auto fill = [&](int c) {
        int k = c * KCH + q * 16;
        uint32_t sg = sb + (uint32_t)(c % 3) * STG_DN + dof;
        cp2(sg + 0u * PL, pah + k);
        cp2(sg + 1u * PL, pal + k);
        cp2(sg + 2u * PL, pbh + k);
        cp2(sg + 3u * PL, pbl + k);
    };

    uint32_t a_off = (uint32_t)(wm * 64 + (lane & 15)) * ROWB + (uint32_t)((lane >> 4) * 16);
    uint32_t b_off = (uint32_t)(wn * 32 + ((lane >> 4) * 8) + (lane & 7)) * ROWB
                   + (uint32_t)(((lane >> 3) & 1) * 16);

    float acc[4][4][4];
#pragma unroll
    for (int i = 0; i < 4; i++)
#pragma unroll
        for (int j = 0; j < 4; j++)
#pragma unroll
            for (int p = 0; p < 4; p++) acc[i][j][p] = 0.f;

    const int NC = KD / KCH;
    fill(0); cp_commit();
    fill(1); cp_commit();

    for (int c = 0; c < NC; c++) {
        cp_wait<1>();
        __syncthreads();
        if (c + 2 < NC) fill(c + 2);
        cp_commit();
        uint32_t sg = sb + (uint32_t)(c % 3) * STG_DN;
#pragma unroll
        for (int s = 0; s < 2; s++) {
            uint32_t ka = a_off + (uint32_t)s * 32u;
            uint32_t kb = b_off + (uint32_t)s * 32u;
            uint32_t ah[4][4], al[4][4];
#pragma unroll
            for (int i = 0; i < 4; i++) {
                uint32_t o = ka + (uint32_t)i * (16u * ROWB);
                ldsm4(ah[i], sg + 0u * PL + o);
                ldsm4(al[i], sg + 1u * PL + o);
            }
            uint32_t bh[2][4], bl[2][4];
#pragma unroll
            for (int jj = 0; jj < 2; jj++) {
                uint32_t o = kb + (uint32_t)jj * (16u * ROWB);
                ldsm4(bh[jj], sg + 2u * PL + o);
                ldsm4(bl[jj], sg + 3u * PL + o);
            }
#pragma unroll
            for (int i = 0; i < 4; i++)
#pragma unroll
                for (int j = 0; j < 4; j++) {
                    const uint32_t* fh = &bh[j >> 1][(j & 1) * 2];
                    const uint32_t* fl = &bl[j >> 1][(j & 1) * 2];
                    mma16816(acc[i][j], ah[i], fh);
                    mma16816(acc[i][j], al[i], fh);
                    mma16816(acc[i][j], ah[i], fl);
                }
        }
    }

    // epilogue: atomic accumulate onto zeroed out
#pragma unroll
    for (int i = 0; i < 4; i++) {
        int rl0 = wm * 64 + i * 16 + (lane >> 2);
        int rl1 = rl0 + 8;
#pragma unroll
        for (int j = 0; j < 4; j++) {
            int cl = wn * 32 + j * 8 + (lane & 3) * 2;
            if (routed) {
                if (rl0 < nvalid) {
                    float w = swt[rl0];
                    float* o = out + (size_t)stok[rl0] * HD + col0 + cl;
                    atomicAdd(&o[0], w * acc[i][j][0]);
                    atomicAdd(&o[1], w * acc[i][j][1]);
                }
                if (rl1 < nvalid) {
                    float w = swt[rl1];
                    float* o = out + (size_t)stok[rl1] * HD + col0 + cl;
                    atomicAdd(&o[0], w * acc[i][j][2]);
                    atomicAdd(&o[1], w * acc[i][j][3]);
                }
            } else {
                float* o0 = out + (size_t)(row0 + rl0) * HD + col0 + cl;
                float* o1 = out + (size_t)(row0 + rl1) * HD + col0 + cl;
                atomicAdd(&o0[0], acc[i][j][0]);
                atomicAdd(&o0[1], acc[i][j][1]);
                atomicAdd(&o1[0], acc[i][j][2]);
                atomicAdd(&o1[1], acc[i][j][3]);
            }
        }
    }
}

// ---------------- launch ----------------
extern "C" void kernel_launch(void* const* d_in, const int* in_sizes, int n_in,
                              void* d_out, int out_size) {
    const float* x   = (const float*)d_in[0];
    const float* gw  = (const float*)d_in[1];
    const float* wg  = (const float*)d_in[2];
    const float* wu  = (const float*)d_in[3];
    const float* wd  = (const float*)d_in[4];
    const float* swg = (const float*)d_in[5];
    const float* swu = (const float*)d_in[6];
    const float* swd = (const float*)d_in[7];
    float* out = (float*)d_out;

    cudaFuncSetAttribute(k_up_all, cudaFuncAttributeMaxDynamicSharedMemorySize, UP_SMEM);
    cudaFuncSetAttribute(k_dn_all, cudaFuncAttributeMaxDynamicSharedMemorySize, DN_SMEM);

    k_init<<<1, 32>>>();
    k_gate<<<NT / 8, 256>>>(x, gw);
    k_scan<<<1, 32>>>();
    k_scatter<<<(NT + 255) / 256, 256>>>();

    // pre-convert everything to bf16 hi/lo
    {
        int n4x = NT * HD / 4;
        k_cvt<<<(n4x + 255) / 256, 256>>>(x, 0, n4x);
        int n4w = NE * FF * HD / 4;
        k_cvt<<<(n4w + 255) / 256, 256>>>(wg, 1, n4w);
        k_cvt<<<(n4w + 255) / 256, 256>>>(wu, 2, n4w);
        k_cvt<<<(n4w + 255) / 256, 256>>>(wd, 3, n4w);
        int n4s = FSS * HD / 4;
        k_cvt<<<(n4s + 255) / 256, 256>>>(swg, 4, n4s);
        k_cvt<<<(n4s + 255) / 256, 256>>>(swu, 5, n4s);
        k_cvt<<<(n4s + 255) / 256, 256>>>(swd, 6, n4s);
    }

    // zero output (both down paths accumulate atomically)
    k_zero<<<(NT * HD / 4 + 255) / 256, 256>>>((float4*)out, NT * HD / 4);

    // fused up (shared + routed), then fused down
    k_up_all<<<UP_ALL, 256, UP_SMEM>>>();
    k_dn_all<<<DN_ALL, 256, DN_SMEM>>>(out);
}

// round 14
// speedup vs baseline: 1.3621x; 1.0058x over previous
#include <cuda_runtime.h>
#include <cstdint>

// ---------------- problem constants ----------------
#define NT   2048
#define HD   2048
#define NE   8
#define FF   1408
#define FSS  2816
#define TMR  128
#define CAPTILES 40
#define CAP (CAPTILES * TMR)

#define KCH   32           // K elements per pipeline stage
#define ROWB  80u          // padded smem row bytes (64B data + 16B pad)
#define PL    10240u       // plane bytes = 128 rows * 80B
#define STG_UP (6u * PL)
#define STG_DN (4u * PL)
#define UP_SMEM (3 * 61440 + 4096)
#define DN_SMEM (3 * 40960 + 4096)

// fused grid decode
#define UP_SH_TILES (16 * 22)     // 352: NT/128 x FSS/128
#define UP_ALL      (UP_SH_TILES + CAPTILES * 11)   // + 40 x FF/128 = 792
#define DN_SH_TILES (16 * 16)     // 256: NT/128 x HD/128
#define DN_ALL      (DN_SH_TILES + CAPTILES * 16)   // + 40 x HD/128 = 896

// ---------------- device scratch ----------------
__device__ int   g_cnt[NE];
__device__ int   g_fill[NE];
__device__ int   g_seg[NE];
__device__ int   g_tidx[NT * 2];
__device__ float g_tw[NT * 2];
__device__ int   g_btok[CAP];
__device__ float g_bw[CAP];

// bf16 hi/lo planes (pre-converted every launch; deterministic)
__device__ uint16_t b_xh[(size_t)NT * HD],   b_xl[(size_t)NT * HD];
__device__ uint16_t b_wgh[(size_t)NE * FF * HD], b_wgl[(size_t)NE * FF * HD];
__device__ uint16_t b_wuh[(size_t)NE * FF * HD], b_wul[(size_t)NE * FF * HD];
__device__ uint16_t b_wdh[(size_t)NE * HD * FF], b_wdl[(size_t)NE * HD * FF];
__device__ uint16_t b_sgh[(size_t)FSS * HD], b_sgl[(size_t)FSS * HD];
__device__ uint16_t b_suh[(size_t)FSS * HD], b_sul[(size_t)FSS * HD];
__device__ uint16_t b_sdh[(size_t)HD * FSS], b_sdl[(size_t)HD * FSS];
__device__ uint16_t b_h1h[(size_t)CAP * FF], b_h1l[(size_t)CAP * FF];
__device__ uint16_t b_h1sh[(size_t)NT * FSS], b_h1sl[(size_t)NT * FSS];

// ---------------- helpers ----------------
__device__ __forceinline__ uint32_t smem_u32(const void* p) {
    uint32_t a;
    asm("{ .reg .u64 t; cvta.to.shared.u64 t, %1; cvt.u32.u64 %0, t; }" : "=r"(a) : "l"(p));
    return a;
}
__device__ __forceinline__ void ldsm4(uint32_t* r, uint32_t addr) {
    asm volatile("ldmatrix.sync.aligned.m8n8.x4.shared.b16 {%0,%1,%2,%3}, [%4];"
        : "=r"(r[0]), "=r"(r[1]), "=r"(r[2]), "=r"(r[3]) : "r"(addr));
}
__device__ __forceinline__ void mma16816(float* c, const uint32_t* a, const uint32_t* b) {
    asm volatile(
        "mma.sync.aligned.m16n8k16.row.col.f32.bf16.bf16.f32 "
        "{%0,%1,%2,%3}, {%4,%5,%6,%7}, {%8,%9}, {%0,%1,%2,%3};"
        : "+f"(c[0]), "+f"(c[1]), "+f"(c[2]), "+f"(c[3])
        : "r"(a[0]), "r"(a[1]), "r"(a[2]), "r"(a[3]), "r"(b[0]), "r"(b[1]));
}
__device__ __forceinline__ void cp2(uint32_t dst, const void* src) {
    asm volatile(
        "cp.async.cg.shared.global [%0], [%1], 16;\n\t"
        "cp.async.cg.shared.global [%2], [%3], 16;"
        :: "r"(dst), "l"(src), "r"(dst + 16u), "l"((const char*)src + 16) : "memory");
}
__device__ __forceinline__ void cp_commit() {
    asm volatile("cp.async.commit_group;" ::: "memory");
}
template <int N> __device__ __forceinline__ void cp_wait() {
    asm volatile("cp.async.wait_group %0;" :: "n"(N) : "memory");
}
// split fp32 pair -> bf16x2 hi + bf16x2 lo, store 4B each
__device__ __forceinline__ void split_store(uint16_t* hi, uint16_t* lo, size_t idx2,
                                            float o0, float o1) {
    uint32_t hp, lp;
    asm("cvt.rn.bf16x2.f32 %0, %1, %2;" : "=r"(hp) : "f"(o1), "f"(o0));
    float r0 = o0 - __uint_as_float(hp << 16);
    float r1 = o1 - __uint_as_float(hp & 0xffff0000u);
    asm("cvt.rn.bf16x2.f32 %0, %1, %2;" : "=r"(lp) : "f"(r1), "f"(r0));
    ((uint32_t*)hi)[idx2] = hp;
    ((uint32_t*)lo)[idx2] = lp;
}

// ---------------- conversion kernel (fp32 -> bf16 hi/lo) ----------------
__global__ void k_cvt(const float* __restrict__ src, int which, int n4) {
    int i = blockIdx.x * blockDim.x + threadIdx.x;
    if (i >= n4) return;
    uint16_t *hi, *lo;
    switch (which) {
        case 0: hi = b_xh;  lo = b_xl;  break;
        case 1: hi = b_wgh; lo = b_wgl; break;
        case 2: hi = b_wuh; lo = b_wul; break;
        case 3: hi = b_wdh; lo = b_wdl; break;
        case 4: hi = b_sgh; lo = b_sgl; break;
        case 5: hi = b_suh; lo = b_sul; break;
        default: hi = b_sdh; lo = b_sdl; break;
    }
    float4 v = ((const float4*)src)[i];
    uint32_t h0, h1, l0, l1;
    asm("cvt.rn.bf16x2.f32 %0, %1, %2;" : "=r"(h0) : "f"(v.y), "f"(v.x));
    asm("cvt.rn.bf16x2.f32 %0, %1, %2;" : "=r"(h1) : "f"(v.w), "f"(v.z));
    float r0 = v.x - __uint_as_float(h0 << 16);
    float r1 = v.y - __uint_as_float(h0 & 0xffff0000u);
    float r2 = v.z - __uint_as_float(h1 << 16);
    float r3 = v.w - __uint_as_float(h1 & 0xffff0000u);
    asm("cvt.rn.bf16x2.f32 %0, %1, %2;" : "=r"(l0) : "f"(r1), "f"(r0));
    asm("cvt.rn.bf16x2.f32 %0, %1, %2;" : "=r"(l1) : "f"(r3), "f"(r2));
    uint2 hv; hv.x = h0; hv.y = h1;
    uint2 lv; lv.x = l0; lv.y = l1;
    ((uint2*)hi)[i] = hv;
    ((uint2*)lo)[i] = lv;
}

// ---------------- zero out ----------------
__global__ void k_zero(float4* __restrict__ o, int n4) {
    int i = blockIdx.x * blockDim.x + threadIdx.x;
    if (i < n4) o[i] = make_float4(0.f, 0.f, 0.f, 0.f);
}

// ---------------- gating ----------------
__global__ void k_init() {
    int i = threadIdx.x;
    if (i < NE) { g_cnt[i] = 0; g_fill[i] = 0; }
}

__global__ void k_gate(const float* __restrict__ x, const float* __restrict__ gw) {
    int gt = blockIdx.x * blockDim.x + threadIdx.x;
    int t = gt >> 5, lane = gt & 31;
    if (t >= NT) return;
    const float* xr = x + (size_t)t * HD;
    float acc[NE];
#pragma unroll
    for (int e = 0; e < NE; e++) acc[e] = 0.f;
    for (int i = lane; i < HD; i += 32) {
        float xv = xr[i];
#pragma unroll
        for (int e = 0; e < NE; e++) acc[e] += xv * gw[e * HD + i];
    }
#pragma unroll
    for (int e = 0; e < NE; e++)
#pragma unroll
        for (int o = 16; o > 0; o >>= 1)
            acc[e] += __shfl_down_sync(0xffffffffu, acc[e], o);
    if (lane == 0) {
        float m = acc[0];
#pragma unroll
        for (int e = 1; e < NE; e++) m = fmaxf(m, acc[e]);
        float p[NE], s = 0.f;
#pragma unroll
        for (int e = 0; e < NE; e++) { p[e] = expf(acc[e] - m); s += p[e]; }
        float inv = 1.f / s;
#pragma unroll
        for (int e = 0; e < NE; e++) p[e] *= inv;
        int i0 = 0; float v0 = p[0];
#pragma unroll
        for (int e = 1; e < NE; e++) if (p[e] > v0) { v0 = p[e]; i0 = e; }
        int i1 = -1; float v1 = -1.f;
#pragma unroll
        for (int e = 0; e < NE; e++) if (e != i0 && p[e] > v1) { v1 = p[e]; i1 = e; }
        float d = 1.f / (v0 + v1 + 1e-20f);
        g_tidx[t * 2 + 0] = i0; g_tw[t * 2 + 0] = v0 * d;
        g_tidx[t * 2 + 1] = i1; g_tw[t * 2 + 1] = v1 * d;
        atomicAdd(&g_cnt[i0], 1);
        atomicAdd(&g_cnt[i1], 1);
    }
}

__global__ void k_scan() {
    if (threadIdx.x == 0) {
        int acc = 0;
        for (int e = 0; e < NE; e++) {
            g_seg[e] = acc;
            acc += (g_cnt[e] + TMR - 1) / TMR * TMR;
        }
    }
}

__global__ void k_scatter() {
    int t = blockIdx.x * blockDim.x + threadIdx.x;
    if (t >= NT) return;
#pragma unroll
    for (int k = 0; k < 2; k++) {
        int e = g_tidx[t * 2 + k];
        float w = g_tw[t * 2 + k];
        int pos = atomicAdd(&g_fill[e], 1);
        g_btok[g_seg[e] + pos] = t;
        g_bw[g_seg[e] + pos] = w;
    }
}

__device__ __forceinline__ void find_expert(int row0, int& e_out, int& valid_out) {
    int e = -1, vr = 0;
    for (int i = 0; i < NE; i++) {
        int st = g_seg[i];
        int sz = (g_cnt[i] + TMR - 1) / TMR * TMR;
        if (row0 >= st && row0 < st + sz) { e = i; vr = g_cnt[i] - (row0 - st); break; }
    }
    e_out = e; valid_out = vr;
}

// ================= fused gate+up GEMM (shared + routed in one launch) =================
// stage planes: Ah, Al, Gh, Gl, Uh, Ul; rows padded to 80B
__global__ __launch_bounds__(256, 1)
void k_up_all() {
    extern __shared__ char smem[];
    uint32_t sb0 = smem_u32(smem);
    uint32_t sb = (sb0 + 127u) & ~127u;
    char* ctrlp = smem + (sb - sb0) + 3 * STG_UP;
    int* sh_meta = (int*)ctrlp;
    int* stok = (int*)(ctrlp + 16);

    int tid = threadIdx.x, lane = tid & 31, wid = tid >> 5;
    int wm = wid & 1, wn = wid >> 1;

    int bid = blockIdx.x;
    int routed, row0, col0;
    if (bid < UP_SH_TILES) {
        routed = 0;
        row0 = (bid / 22) * TMR;
        col0 = (bid % 22) * TMR;
    } else {
        routed = 1;
        int r = bid - UP_SH_TILES;
        row0 = (r / 11) * TMR;
        col0 = (r % 11) * TMR;
    }

    int e = 0, nvalid = TMR;
    if (routed) {
        if (tid == 0) {
            int ee, vv; find_expert(row0, ee, vv);
            sh_meta[0] = ee; sh_meta[1] = vv;
        }
        __syncthreads();
        e = sh_meta[0];
        int v = sh_meta[1];
        if (e < 0 || v <= 0) return;
        nvalid = v > TMR ? TMR : v;
        if (tid < TMR) stok[tid] = (tid < nvalid) ? g_btok[row0 + tid] : 0;
        __syncthreads();
    }

    // fill mapping: thread owns (row = tid>>1, 16-elem half q = tid&1)
    int frow = tid >> 1, q = tid & 1;
    uint32_t dof = (uint32_t)frow * ROWB + (uint32_t)q * 32u;

    const uint16_t *pah, *pal, *pgh, *pgl, *puh, *pul;
    if (routed) {
        int tok = stok[frow];
        pah = b_xh + (size_t)tok * HD; pal = b_xl + (size_t)tok * HD;
        size_t wo = (size_t)e * FF * HD + (size_t)(col0 + frow) * HD;
        pgh = b_wgh + wo; pgl = b_wgl + wo;
        puh = b_wuh + wo; pul = b_wul + wo;
    } else {
        pah = b_xh + (size_t)(row0 + frow) * HD; pal = b_xl + (size_t)(row0 + frow) * HD;
        size_t wo = (size_t)(col0 + frow) * HD;
        pgh = b_sgh + wo; pgl = b_sgl + wo;
        puh = b_suh + wo; pul = b_sul + wo;
    }

    auto fill = [&](int c) {
        int k = c * KCH + q * 16;
        uint32_t sg = sb + (uint32_t)(c % 3) * STG_UP + dof;
        cp2(sg + 0u * PL, pah + k);
        cp2(sg + 1u * PL, pal + k);
        cp2(sg + 2u * PL, pgh + k);
        cp2(sg + 3u * PL, pgl + k);
        cp2(sg + 4u * PL, puh + k);
        cp2(sg + 5u * PL, pul + k);
    };

    uint32_t a_off = (uint32_t)(wm * 64 + (lane & 15)) * ROWB + (uint32_t)((lane >> 4) * 16);
    uint32_t b_off = (uint32_t)(wn * 32 + ((lane >> 4) * 8) + (lane & 7)) * ROWB
                   + (uint32_t)(((lane >> 3) & 1) * 16);

    float accg[4][4][4], accu[4][4][4];
#pragma unroll
    for (int i = 0; i < 4; i++)
#pragma unroll
        for (int j = 0; j < 4; j++)
#pragma unroll
            for (int p = 0; p < 4; p++) { accg[i][j][p] = 0.f; accu[i][j][p] = 0.f; }

    const int NC = HD / KCH;
    fill(0); cp_commit();
    fill(1); cp_commit();

    for (int c = 0; c < NC; c++) {
        cp_wait<1>();
        __syncthreads();
        if (c + 2 < NC) fill(c + 2);
        cp_commit();
        uint32_t sg = sb + (uint32_t)(c % 3) * STG_UP;
#pragma unroll
        for (int s = 0; s < 2; s++) {
            uint32_t ka = a_off + (uint32_t)s * 32u;
            uint32_t kb = b_off + (uint32_t)s * 32u;
            // issue ALL ldsm for this s up-front so latency hides under MMAs
            uint32_t ah[4][4], al[4][4];
#pragma unroll
            for (int i = 0; i < 4; i++) {
                uint32_t o = ka + (uint32_t)i * (16u * ROWB);
                ldsm4(ah[i], sg + 0u * PL + o);
                ldsm4(al[i], sg + 1u * PL + o);
            }
            uint32_t bgh[2][4], bgl[2][4], buh[2][4], bul[2][4];
#pragma unroll
            for (int jj = 0; jj < 2; jj++) {
                uint32_t o = kb + (uint32_t)jj * (16u * ROWB);
                ldsm4(bgh[jj], sg + 2u * PL + o);
                ldsm4(bgl[jj], sg + 3u * PL + o);
                ldsm4(buh[jj], sg + 4u * PL + o);
                ldsm4(bul[jj], sg + 5u * PL + o);
            }
#pragma unroll
            for (int i = 0; i < 4; i++)
#pragma unroll
                for (int j = 0; j < 4; j++) {
                    const uint32_t* fh = &bgh[j >> 1][(j & 1) * 2];
                    const uint32_t* fl = &bgl[j >> 1][(j & 1) * 2];
                    mma16816(accg[i][j], ah[i], fh);
                    mma16816(accg[i][j], al[i], fh);
                    mma16816(accg[i][j], ah[i], fl);
                }
#pragma unroll
            for (int i = 0; i < 4; i++)
#pragma unroll
                for (int j = 0; j < 4; j++) {
                    const uint32_t* fh = &buh[j >> 1][(j & 1) * 2];
                    const uint32_t* fl = &bul[j >> 1][(j & 1) * 2];
                    mma16816(accu[i][j], ah[i], fh);
                    mma16816(accu[i][j], al[i], fh);
                    mma16816(accu[i][j], ah[i], fl);
                }
        }
    }

    // epilogue: silu(g)*u -> bf16 hi/lo h1
    const int LDC = routed ? FF : FSS;
    uint16_t* dh = routed ? b_h1h : b_h1sh;
    uint16_t* dl = routed ? b_h1l : b_h1sl;
#pragma unroll
    for (int i = 0; i < 4; i++) {
        int rl0 = wm * 64 + i * 16 + (lane >> 2);
        int rl1 = rl0 + 8;
#pragma unroll
        for (int j = 0; j < 4; j++) {
            int cl = wn * 32 + j * 8 + (lane & 3) * 2;
            if (!routed || rl0 < nvalid) {
                float g0 = accg[i][j][0], g1 = accg[i][j][1];
                float o0 = g0 / (1.f + __expf(-g0)) * accu[i][j][0];
                float o1 = g1 / (1.f + __expf(-g1)) * accu[i][j][1];
                split_store(dh, dl, ((size_t)(row0 + rl0) * LDC + col0 + cl) >> 1, o0, o1);
            }
            if (!routed || rl1 < nvalid) {
                float g0 = accg[i][j][2], g1 = accg[i][j][3];
                float o0 = g0 / (1.f + __expf(-g0)) * accu[i][j][2];
                float o1 = g1 / (1.f + __expf(-g1)) * accu[i][j][3];
                split_store(dh, dl, ((size_t)(row0 + rl1) * LDC + col0 + cl) >> 1, o0, o1);
            }
        }
    }
}

// ================= fused down GEMM (shared + routed, all-atomic epilogue) =================
// stage planes: Ah, Al, Bh, Bl
__global__ __launch_bounds__(256, 1)
void k_dn_all(float* __restrict__ out) {
    extern __shared__ char smem[];
    uint32_t sb0 = smem_u32(smem);
    uint32_t sb = (sb0 + 127u) & ~127u;
    char* ctrlp = smem + (sb - sb0) + 3 * STG_DN;
    int* sh_meta = (int*)ctrlp;
    int* stok = (int*)(ctrlp + 16);
    float* swt = (float*)(ctrlp + 16 + 512);

    int tid = threadIdx.x, lane = tid & 31, wid = tid >> 5;
    int wm = wid & 1, wn = wid >> 1;

    int bid = blockIdx.x;
    int routed, row0, col0;
    if (bid < DN_SH_TILES) {
        routed = 0;
        row0 = (bid / 16) * TMR;
        col0 = (bid % 16) * TMR;
    } else {
        routed = 1;
        int r = bid - DN_SH_TILES;
        row0 = (r / 16) * TMR;
        col0 = (r % 16) * TMR;
    }

    int e = 0, nvalid = TMR;
    if (routed) {
        if (tid == 0) {
            int ee, vv; find_expert(row0, ee, vv);
            sh_meta[0] = ee; sh_meta[1] = vv;
        }
        __syncthreads();
        e = sh_meta[0];
        int v = sh_meta[1];
        if (e < 0 || v <= 0) return;
        nvalid = v > TMR ? TMR : v;
        if (tid < TMR) {
            bool ok = tid < nvalid;
            stok[tid] = ok ? g_btok[row0 + tid] : 0;
            swt[tid]  = ok ? g_bw[row0 + tid]   : 0.f;
        }
        __syncthreads();
    }

    const int KD = routed ? FF : FSS;
    int frow = tid >> 1, q = tid & 1;
    uint32_t dof = (uint32_t)frow * ROWB + (uint32_t)q * 32u;

    const uint16_t* pah = (routed ? b_h1h : b_h1sh) + (size_t)(row0 + frow) * KD;
    const uint16_t* pal = (routed ? b_h1l : b_h1sl) + (size_t)(row0 + frow) * KD;
    const uint16_t* pbh = (routed ? b_wdh + (size_t)e * HD * FF : b_sdh)
                          + (size_t)(col0 + frow) * KD;
    const uint16_t* pbl = (routed ? b_wdl + (size_t)e * HD * FF : b_sdl)
                          + (size_t)(col0 + frow) * KD;

    auto fill = [&](int c) {
        int k = c * KCH + q * 16;
        uint32_t sg = sb + (uint32_t)(c % 3) * STG_DN + dof;
        cp2(sg + 0u * PL, pah + k);
        cp2(sg + 1u * PL, pal + k);
        cp2(sg + 2u * PL, pbh + k);
        cp2(sg + 3u * PL, pbl + k);
    };

    uint32_t a_off = (uint32_t)(wm * 64 + (lane & 15)) * ROWB + (uint32_t)((lane >> 4) * 16);
    uint32_t b_off = (uint32_t)(wn * 32 + ((lane >> 4) * 8) + (lane & 7)) * ROWB
                   + (uint32_t)(((lane >> 3) & 1) * 16);

    float acc[4][4][4];
#pragma unroll
    for (int i = 0; i < 4; i++)
#pragma unroll
        for (int j = 0; j < 4; j++)
#pragma unroll
            for (int p = 0; p < 4; p++) acc[i][j][p] = 0.f;

    const int NC = KD / KCH;
    fill(0); cp_commit();
    fill(1); cp_commit();

    for (int c = 0; c < NC; c++) {
        cp_wait<1>();
        __syncthreads();
        if (c + 2 < NC) fill(c + 2);
        cp_commit();
        uint32_t sg = sb + (uint32_t)(c % 3) * STG_DN;
#pragma unroll
        for (int s = 0; s < 2; s++) {
            uint32_t ka = a_off + (uint32_t)s * 32u;
            uint32_t kb = b_off + (uint32_t)s * 32u;
            uint32_t ah[4][4], al[4][4];
#pragma unroll
            for (int i = 0; i < 4; i++) {
                uint32_t o = ka + (uint32_t)i * (16u * ROWB);
                ldsm4(ah[i], sg + 0u * PL + o);
                ldsm4(al[i], sg + 1u * PL + o);
            }
            uint32_t bh[2][4], bl[2][4];
#pragma unroll
            for (int jj = 0; jj < 2; jj++) {
                uint32_t o = kb + (uint32_t)jj * (16u * ROWB);
                ldsm4(bh[jj], sg + 2u * PL + o);
                ldsm4(bl[jj], sg + 3u * PL + o);
            }
#pragma unroll
            for (int i = 0; i < 4; i++)
#pragma unroll
                for (int j = 0; j < 4; j++) {
                    const uint32_t* fh = &bh[j >> 1][(j & 1) * 2];
                    const uint32_t* fl = &bl[j >> 1][(j & 1) * 2];
                    mma16816(acc[i][j], ah[i], fh);
                    mma16816(acc[i][j], al[i], fh);
                    mma16816(acc[i][j], ah[i], fl);
                }
        }
    }

    // epilogue: atomic accumulate onto zeroed out
#pragma unroll
    for (int i = 0; i < 4; i++) {
        int rl0 = wm * 64 + i * 16 + (lane >> 2);
        int rl1 = rl0 + 8;
#pragma unroll
        for (int j = 0; j < 4; j++) {
            int cl = wn * 32 + j * 8 + (lane & 3) * 2;
            if (routed) {
                if (rl0 < nvalid) {
                    float w = swt[rl0];
                    float* o = out + (size_t)stok[rl0] * HD + col0 + cl;
                    atomicAdd(&o[0], w * acc[i][j][0]);
                    atomicAdd(&o[1], w * acc[i][j][1]);
                }
                if (rl1 < nvalid) {
                    float w = swt[rl1];
                    float* o = out + (size_t)stok[rl1] * HD + col0 + cl;
                    atomicAdd(&o[0], w * acc[i][j][2]);
                    atomicAdd(&o[1], w * acc[i][j][3]);
                }
            } else {
                float* o0 = out + (size_t)(row0 + rl0) * HD + col0 + cl;
                float* o1 = out + (size_t)(row0 + rl1) * HD + col0 + cl;
                atomicAdd(&o0[0], acc[i][j][0]);
                atomicAdd(&o0[1], acc[i][j][1]);
                atomicAdd(&o1[0], acc[i][j][2]);
                atomicAdd(&o1[1], acc[i][j][3]);
            }
        }
    }
}

// ---------------- launch ----------------
extern "C" void kernel_launch(void* const* d_in, const int* in_sizes, int n_in,
                              void* d_out, int out_size) {
    const float* x   = (const float*)d_in[0];
    const float* gw  = (const float*)d_in[1];
    const float* wg  = (const float*)d_in[2];
    const float* wu  = (const float*)d_in[3];
    const float* wd  = (const float*)d_in[4];
    const float* swg = (const float*)d_in[5];
    const float* swu = (const float*)d_in[6];
    const float* swd = (const float*)d_in[7];
    float* out = (float*)d_out;

    cudaFuncSetAttribute(k_up_all, cudaFuncAttributeMaxDynamicSharedMemorySize, UP_SMEM);
    cudaFuncSetAttribute(k_dn_all, cudaFuncAttributeMaxDynamicSharedMemorySize, DN_SMEM);

    k_init<<<1, 32>>>();
    k_gate<<<NT / 8, 256>>>(x, gw);
    k_scan<<<1, 32>>>();
    k_scatter<<<(NT + 255) / 256, 256>>>();

    // pre-convert everything to bf16 hi/lo
    {
        int n4x = NT * HD / 4;
        k_cvt<<<(n4x + 255) / 256, 256>>>(x, 0, n4x);
        int n4w = NE * FF * HD / 4;
        k_cvt<<<(n4w + 255) / 256, 256>>>(wg, 1, n4w);
        k_cvt<<<(n4w + 255) / 256, 256>>>(wu, 2, n4w);
        k_cvt<<<(n4w + 255) / 256, 256>>>(wd, 3, n4w);
        int n4s = FSS * HD / 4;
        k_cvt<<<(n4s + 255) / 256, 256>>>(swg, 4, n4s);
        k_cvt<<<(n4s + 255) / 256, 256>>>(swu, 5, n4s);
        k_cvt<<<(n4s + 255) / 256, 256>>>(swd, 6, n4s);
    }

    // zero output (both down paths accumulate atomically)
    k_zero<<<(NT * HD / 4 + 255) / 256, 256>>>((float4*)out, NT * HD / 4);

    // fused up (shared + routed), then fused down
    k_up_all<<<UP_ALL, 256, UP_SMEM>>>();
    k_dn_all<<<DN_ALL, 256, DN_SMEM>>>(out);
}